// round 1
// baseline (speedup 1.0000x reference)
#include <cuda_runtime.h>
#include <cuda_bf16.h>
#include <math.h>

// Problem constants (dataset-fixed)
#define MAXN 100000
#define MAXE 1600000
#define FIN  512
#define HID  64
#define NCLS 16

// ---------------- device scratch (no allocation allowed) ----------------
__device__ float g_support1[MAXN * HID];     // x @ W1
__device__ float g_h[MAXN * HID];            // relu(A @ support1 + b1)
__device__ float g_support2[MAXN * NCLS];    // h @ W2
__device__ int   g_cnt[MAXN];
__device__ int   g_incl[MAXN];
__device__ int   g_rowoff[MAXN + 1];
__device__ int   g_blockSums[512];
__device__ int   g_blockOff[512];
__device__ int   g_csr_src[MAXE];
__device__ float g_csr_val[MAXE];

// ---------------- small utilities ----------------
__device__ __forceinline__ int warp_incl_scan(int v) {
    int lane = threadIdx.x & 31;
#pragma unroll
    for (int d = 1; d < 32; d <<= 1) {
        int t = __shfl_up_sync(0xffffffffu, v, d);
        if (lane >= d) v += t;
    }
    return v;
}

__global__ void zero_cnt_kernel(int n) {
    int i = blockIdx.x * 256 + threadIdx.x;
    if (i < n) g_cnt[i] = 0;
}

__global__ void hist_kernel(const int* __restrict__ dst, int e) {
    int i = blockIdx.x * 256 + threadIdx.x;
    if (i < e) atomicAdd(&g_cnt[dst[i]], 1);
}

// per-512-block inclusive scan of g_cnt -> g_incl, block totals -> g_blockSums
__global__ void scan1_kernel(int n) {
    __shared__ int warpS[16];
    int tid = threadIdx.x;
    int gid = blockIdx.x * 512 + tid;
    int v = (gid < n) ? g_cnt[gid] : 0;
    int s = warp_incl_scan(v);
    int wid = tid >> 5, lane = tid & 31;
    if (lane == 31) warpS[wid] = s;
    __syncthreads();
    if (wid == 0) {
        int wv = (lane < 16) ? warpS[lane] : 0;
        int ws = warp_incl_scan(wv);
        if (lane < 16) warpS[lane] = ws;
    }
    __syncthreads();
    int off = (wid > 0) ? warpS[wid - 1] : 0;
    s += off;
    if (gid < n) g_incl[gid] = s;
    if (tid == 511) g_blockSums[blockIdx.x] = s;
}

// exclusive scan of block sums (nb <= 256) -> g_blockOff
__global__ void scan2_kernel(int nb) {
    __shared__ int warpS[8];
    int tid = threadIdx.x;
    int v = (tid < nb) ? g_blockSums[tid] : 0;
    int s = warp_incl_scan(v);
    int wid = tid >> 5, lane = tid & 31;
    if (lane == 31) warpS[wid] = s;
    __syncthreads();
    if (wid == 0) {
        int wv = (lane < 8) ? warpS[lane] : 0;
        int ws = warp_incl_scan(wv);
        if (lane < 8) warpS[lane] = ws;
    }
    __syncthreads();
    int off = (wid > 0) ? warpS[wid - 1] : 0;
    if (tid < nb) g_blockOff[tid] = s + off - v;  // exclusive
}

// row offsets: rowoff[0]=0 ; rowoff[i+1] = incl[i] + blockOff[i/512]
__global__ void scan3_kernel(int n) {
    int gid = blockIdx.x * 256 + threadIdx.x;
    if (gid == 0) g_rowoff[0] = 0;
    if (gid < n) g_rowoff[gid + 1] = g_incl[gid] + g_blockOff[gid >> 9];
}

__global__ void scatter_kernel(const int* __restrict__ src,
                               const int* __restrict__ dst,
                               const float* __restrict__ val, int e) {
    int i = blockIdx.x * 256 + threadIdx.x;
    if (i < e) {
        int d = dst[i];
        int p = g_rowoff[d] + atomicAdd(&g_cnt[d], 1);
        g_csr_src[p] = src[i];
        g_csr_val[p] = val[i];
    }
}

// ---------------- GEMM1: support1 = x[N,512] @ W1[512,64] ----------------
// 256 threads, tile 64x64, K-chunk 32, 4x4 per-thread register block.
#define BM 64
#define BN 64
#define BK 32
__global__ __launch_bounds__(256) void gemm1_kernel(const float* __restrict__ x,
                                                    const float* __restrict__ W1,
                                                    int N) {
    __shared__ float As[BK][BM + 4];  // transposed x tile
    __shared__ float Bs[BK][BN + 4];
    int tid = threadIdx.x;
    int tx = tid & 15;        // col group
    int ty = tid >> 4;        // row group
    int block_row = blockIdx.x * BM;

    float acc[4][4];
#pragma unroll
    for (int i = 0; i < 4; i++)
#pragma unroll
        for (int j = 0; j < 4; j++) acc[i][j] = 0.f;

    int lrow = tid >> 2;            // 0..63
    int lk = (tid & 3) * 8;         // 0,8,16,24
    int wk = tid >> 3;              // 0..31
    int wc = (tid & 7) * 8;         // 0..56
    bool rvalid = (block_row + lrow) < N;
    const float* xrow = x + (size_t)(block_row + lrow) * FIN;

    for (int k0 = 0; k0 < FIN; k0 += BK) {
        float4 a0, a1;
        if (rvalid) {
            a0 = *(const float4*)(xrow + k0 + lk);
            a1 = *(const float4*)(xrow + k0 + lk + 4);
        } else {
            a0 = make_float4(0, 0, 0, 0);
            a1 = make_float4(0, 0, 0, 0);
        }
        As[lk + 0][lrow] = a0.x; As[lk + 1][lrow] = a0.y;
        As[lk + 2][lrow] = a0.z; As[lk + 3][lrow] = a0.w;
        As[lk + 4][lrow] = a1.x; As[lk + 5][lrow] = a1.y;
        As[lk + 6][lrow] = a1.z; As[lk + 7][lrow] = a1.w;

        float4 b0 = *(const float4*)(W1 + (size_t)(k0 + wk) * HID + wc);
        float4 b1 = *(const float4*)(W1 + (size_t)(k0 + wk) * HID + wc + 4);
        *(float4*)&Bs[wk][wc] = b0;
        *(float4*)&Bs[wk][wc + 4] = b1;
        __syncthreads();

#pragma unroll
        for (int k = 0; k < BK; k++) {
            float4 ra = *(const float4*)&As[k][ty * 4];
            float4 rb = *(const float4*)&Bs[k][tx * 4];
            float av[4] = {ra.x, ra.y, ra.z, ra.w};
            float bv[4] = {rb.x, rb.y, rb.z, rb.w};
#pragma unroll
            for (int i = 0; i < 4; i++)
#pragma unroll
                for (int j = 0; j < 4; j++) acc[i][j] += av[i] * bv[j];
        }
        __syncthreads();
    }

#pragma unroll
    for (int i = 0; i < 4; i++) {
        int r = block_row + ty * 4 + i;
        if (r < N) {
            float4 o = make_float4(acc[i][0], acc[i][1], acc[i][2], acc[i][3]);
            *(float4*)&g_support1[(size_t)r * HID + tx * 4] = o;
        }
    }
}

// ---------------- SpMM1: h = relu(A @ support1 + b1) (pull, warp/node) ----
__global__ __launch_bounds__(256) void spmm1_kernel(const float* __restrict__ b1, int N) {
    int warp = (blockIdx.x * blockDim.x + threadIdx.x) >> 5;
    int lane = threadIdx.x & 31;
    if (warp >= N) return;
    int s = g_rowoff[warp];
    int e = g_rowoff[warp + 1];
    float a0 = 0.f, a1 = 0.f;
    for (int i = s; i < e; i++) {
        int src = g_csr_src[i];
        float v = g_csr_val[i];
        const float* row = &g_support1[(size_t)src * HID];
        a0 += v * row[lane];
        a1 += v * row[lane + 32];
    }
    float h0 = a0 + b1[lane];
    float h1 = a1 + b1[lane + 32];
    g_h[(size_t)warp * HID + lane]      = h0 > 0.f ? h0 : 0.f;
    g_h[(size_t)warp * HID + lane + 32] = h1 > 0.f ? h1 : 0.f;
}

// ---------------- GEMM2: support2 = h[N,64] @ W2[64,16] ----------------
// Each warp: 2 rows (lanes 0-15 row A, 16-31 row B), 1 col per lane.
__global__ __launch_bounds__(256) void gemm2_kernel(const float* __restrict__ W2, int N) {
    __shared__ float Ws[HID * NCLS];
    int tid = threadIdx.x;
    for (int i = tid; i < HID * NCLS; i += 256) Ws[i] = W2[i];
    __syncthreads();
    int lane = tid & 31, wid = tid >> 5;
    int row = (blockIdx.x * 8 + wid) * 2 + (lane >> 4);
    int col = lane & 15;
    if (row >= N) return;
    const float* hr = &g_h[(size_t)row * HID];
    float acc = 0.f;
#pragma unroll
    for (int k = 0; k < HID; k++) acc += hr[k] * Ws[k * NCLS + col];
    g_support2[(size_t)row * NCLS + col] = acc;
}

// ------- SpMM2 + b2 + softmax: out = softmax(A @ support2 + b2) ---------
// Warp per node; 2 edges per iteration (lanes 0-15 edge i, 16-31 edge i+1).
__global__ __launch_bounds__(256) void spmm2_softmax_kernel(const float* __restrict__ b2,
                                                            float* __restrict__ out, int N) {
    int warp = (blockIdx.x * blockDim.x + threadIdx.x) >> 5;
    int lane = threadIdx.x & 31;
    if (warp >= N) return;
    int s = g_rowoff[warp];
    int e = g_rowoff[warp + 1];
    int col = lane & 15;
    float acc = 0.f;
    for (int i = s; i < e; i += 2) {
        int idx = i + (lane >> 4);
        if (idx < e) {
            int src = g_csr_src[idx];
            float v = g_csr_val[idx];
            acc += v * g_support2[(size_t)src * NCLS + col];
        }
    }
    // fold upper 16 lanes into lower 16
    acc += __shfl_down_sync(0xffffffffu, acc, 16);
    float logit = acc + b2[col];
    // softmax across the 16-lane group (xor widths stay within the half-warp)
    float m = logit;
#pragma unroll
    for (int d = 8; d >= 1; d >>= 1) m = fmaxf(m, __shfl_xor_sync(0xffffffffu, m, d));
    float ev = __expf(logit - m);
    float sum = ev;
#pragma unroll
    for (int d = 8; d >= 1; d >>= 1) sum += __shfl_xor_sync(0xffffffffu, sum, d);
    if (lane < 16) out[(size_t)warp * NCLS + col] = ev / sum;
}

// ---------------- launch ----------------
extern "C" void kernel_launch(void* const* d_in, const int* in_sizes, int n_in,
                              void* d_out, int out_size) {
    const float* x        = (const float*)d_in[0];
    const int*   edge_src = (const int*)d_in[1];
    const int*   edge_dst = (const int*)d_in[2];
    const float* edge_val = (const float*)d_in[3];
    const float* W1       = (const float*)d_in[4];
    const float* b1       = (const float*)d_in[5];
    const float* W2       = (const float*)d_in[6];
    const float* b2       = (const float*)d_in[7];
    float* out = (float*)d_out;

    int E = in_sizes[1];
    int N = in_sizes[0] / FIN;

    int nblkN = (N + 255) / 256;
    int nblkE = (E + 255) / 256;
    int nbScan = (N + 511) / 512;

    // CSR build (by dst)
    zero_cnt_kernel<<<nblkN, 256>>>(N);
    hist_kernel<<<nblkE, 256>>>(edge_dst, E);
    scan1_kernel<<<nbScan, 512>>>(N);
    scan2_kernel<<<1, 256>>>(nbScan);
    scan3_kernel<<<nblkN, 256>>>(N);
    zero_cnt_kernel<<<nblkN, 256>>>(N);
    scatter_kernel<<<nblkE, 256>>>(edge_src, edge_dst, edge_val, E);

    // Layer 1
    gemm1_kernel<<<(N + BM - 1) / BM, 256>>>(x, W1, N);
    spmm1_kernel<<<(N + 7) / 8, 256>>>(b1, N);

    // Layer 2 + softmax
    gemm2_kernel<<<(N + 15) / 16, 256>>>(W2, N);
    spmm2_softmax_kernel<<<(N + 7) / 8, 256>>>(b2, out, N);
}